// round 17
// baseline (speedup 1.0000x reference)
#include <cuda_runtime.h>
#include <cuda_fp16.h>
#include <cuda_bf16.h>

namespace {

constexpr int B = 16, H = 512, W = 512;
constexpr int TPX    = 16;             // threads in x; each handles packed pixels 2tx, 2tx+1
constexpr int TYB    = 16;             // threads in y
constexpr int TILE_W = 64;             // tile width in pixels (halves packed 32 apart)
constexpr int TILE_H = 32;             // tile height: each thread does rows ty and ty+16
constexpr int NPACK  = 36;             // packed columns incl. halo (32 + 4)
constexpr int NPAIR  = 17;             // distinct pair-merges per row: pairs (2k+1, 2k+2), k=0..16
constexpr int NTHREADS = TPX * TYB;    // 256
constexpr int NTASKS  = NPACK * TILE_H; // 1152 column-sort tasks per block
constexpr int NPTASKS = NPAIR * TILE_H; // 544 pair-merge tasks per block

__device__ __forceinline__ int reflect(int i, int n) {
    if (i < 0) i = -i;
    if (i >= n) i = 2 * n - 2 - i;
    return i;
}

// packed descending compare-exchange on 2 independent lanes: a >= b per lane
__device__ __forceinline__ void ceD(__half2& a, __half2& b) {
    __half2 mx = __hmax2(a, b);
    __half2 mn = __hmin2(a, b);
    a = mx; b = mn;
}

// greatest power of two strictly less than N (N >= 2)
template<int N> struct GP2    { static constexpr int value = 2 * GP2<(N + 1) / 2>::value; };
template<>      struct GP2<2> { static constexpr int value = 1; };
template<>      struct GP2<1> { static constexpr int value = 1; };

// Lang's arbitrary-N bitonic merge, descending output. Input bitonic (mountain).
template<int N>
__device__ __forceinline__ void bmergeD(__half2* v) {
    if constexpr (N > 1) {
        constexpr int K = GP2<N>::value;
        #pragma unroll
        for (int i = 0; i < N - K; i++) ceD(v[i], v[i + K]);
        bmergeD<K>(v);
        bmergeD<N - K>(v + K);
    }
}

// optimal 9-CE sorting network for 5 elements (descending), packed
__device__ __forceinline__ void sort5D(__half2* a) {
    ceD(a[0], a[1]); ceD(a[3], a[4]); ceD(a[2], a[4]); ceD(a[2], a[3]);
    ceD(a[1], a[4]); ceD(a[0], a[3]); ceD(a[0], a[2]); ceD(a[1], a[3]);
    ceD(a[1], a[2]);
}

// merge two sorted-desc-5 lists into sorted-desc-10 (15 CE)
__device__ __forceinline__ void merge55(const __half2* a, const __half2* b, __half2* out10) {
    #pragma unroll
    for (int j = 0; j < 5; j++) out10[j] = a[4 - j];   // ascending
    #pragma unroll
    for (int j = 0; j < 5; j++) out10[5 + j] = b[j];   // descending
    bmergeD<10>(out10);
}

// Algebraic final merge: sum of top-9 of (sorted-desc-9 u[0..8]) ∪ (sorted-desc-5 c).
// Bitonic split of asc(u)++desc(c): top-8 = {u0,u1,u2, max(u7-i,ci)}, 9th = max of
// the bitonic remainder {u8, min(u7-i,ci)}. Exact selection; fp32 sum.
// (sux, suy) = precomputed u0+u1+u2 per packed lane.
__device__ __forceinline__ float2 top9_sum(const __half2* u, const __half2* c,
                                           float sux, float suy) {
    __half2 mx0 = __hmax2(u[7], c[0]), mn0 = __hmin2(u[7], c[0]);
    __half2 mx1 = __hmax2(u[6], c[1]), mn1 = __hmin2(u[6], c[1]);
    __half2 mx2 = __hmax2(u[5], c[2]), mn2 = __hmin2(u[5], c[2]);
    __half2 mx3 = __hmax2(u[4], c[3]), mn3 = __hmin2(u[4], c[3]);
    __half2 mx4 = __hmax2(u[3], c[4]), mn4 = __hmin2(u[3], c[4]);
    __half2 m9 = __hmax2(__hmax2(__hmax2(u[8], mn0), __hmax2(mn1, mn2)),
                         __hmax2(mn3, mn4));
    const float2 f0 = __half22float2(mx0);
    const float2 f1 = __half22float2(mx1);
    const float2 f2 = __half22float2(mx2);
    const float2 f3 = __half22float2(mx3);
    const float2 f4 = __half22float2(mx4);
    const float2 f9 = __half22float2(m9);
    float sx = sux + f0.x + f1.x + f2.x + f3.x + f4.x + f9.x;
    float sy = suy + f0.y + f1.y + f2.y + f3.y + f4.y + f9.y;
    return make_float2(sx, sy);
}

using ScTile = __half2[5][TILE_H][NPACK];
using PmTile = __half2[TILE_H][NPAIR + 1][10];   // +1 pad; [k][10] = sorted-desc pair-merge

// One pixel-pair-unit: two adjacent packed pixels (4 real pixels) at tile row cy.
__device__ __forceinline__ void phase2_unit(const ScTile& sc, const PmTile& pm,
                                            int cy, int tx, float* __restrict__ orow) {
    const int p0 = 2 * tx;

    // A10 = pair-merge k=tx (cols p0+1,p0+2); B10 = pair-merge k=tx+1 (cols p0+3,p0+4)
    __half2 A10[10], B10[10];
    #pragma unroll
    for (int j = 0; j < 10; j += 2) {
        const float2 ra = *reinterpret_cast<const float2*>(&pm[cy][tx][j]);
        const float2 rb = *reinterpret_cast<const float2*>(&pm[cy][tx + 1][j]);
        A10[j]     = *reinterpret_cast<const __half2*>(&ra.x);
        A10[j + 1] = *reinterpret_cast<const __half2*>(&ra.y);
        B10[j]     = *reinterpret_cast<const __half2*>(&rb.x);
        B10[j + 1] = *reinterpret_cast<const __half2*>(&rb.y);
    }

    // private edge columns
    __half2 c0[5], c5[5];
    #pragma unroll
    for (int j = 0; j < 5; j++) {
        c0[j] = sc[j][cy][p0];
        c5[j] = sc[j][cy][p0 + 5];
    }

    // shared top-9 (sorted) of the 4 middle columns
    __half2 u[20];
    #pragma unroll
    for (int j = 0; j < 10; j++) u[j] = A10[9 - j];    // ascending
    #pragma unroll
    for (int j = 0; j < 10; j++) u[10 + j] = B10[j];   // descending
    bmergeD<20>(u);                                    // only u[0..8] used -> rest DCE'd

    // shared partial sum u0+u1+u2 (always in the top-9 of either pixel)
    const float2 g0 = __half22float2(u[0]);
    const float2 g1 = __half22float2(u[1]);
    const float2 g2 = __half22float2(u[2]);
    const float sux = g0.x + g1.x + g2.x;
    const float suy = g0.y + g1.y + g2.y;

    // per-pixel algebraic final merges with the private edge columns
    const float2 s0 = top9_sum(u, c0, sux, suy);
    const float2 s1 = top9_sum(u, c5, sux, suy);

    orow[p0]      = s0.x * (1.0f / 9.0f);
    orow[p0 + 1]  = s1.x * (1.0f / 9.0f);
    orow[p0 + 32] = s0.y * (1.0f / 9.0f);
    orow[p0 + 33] = s1.y * (1.0f / 9.0f);
}

__global__ __launch_bounds__(NTHREADS)
void ordfilter_kernel(const float* __restrict__ inp, float* __restrict__ out) {
    // sc[j][cy][p] : j-th largest of the vertical 5-window at packed column p
    //   lane .x = image column x0 + p - 2;  lane .y = image column x0 + 32 + p - 2
    __shared__ alignas(16) ScTile sc;
    // pm[cy][k][j] : j-th largest of merge55(packed cols 2k+1, 2k+2) at row cy
    __shared__ alignas(16) PmTile pm;

    const int b   = blockIdx.z;
    const int x0  = blockIdx.x * TILE_W;
    const int y0  = blockIdx.y * TILE_H;
    const int tx  = threadIdx.x;           // 0..15
    const int ty  = threadIdx.y;           // 0..15
    const int tid = ty * TPX + tx;
    const float* __restrict__ img = inp + (size_t)b * H * W;

    // ---- Phase 1: packed vertical column sorts (statically unrolled tasks) ----
    #pragma unroll
    for (int k = 0; k < 5; k++) {
        const int task = tid + k * NTHREADS;
        if (k < 4 || task < NTASKS) {      // k<4 always in range (1024 < 1152)
            const int p  = task % NPACK;
            const int cy = task / NPACK;
            const int gxL = reflect(x0 + p - 2, W);
            const int gxR = reflect(x0 + 32 + p - 2, W);
            __half2 v[5];
            #pragma unroll
            for (int j = 0; j < 5; j++) {
                const int yy = reflect(y0 + cy - 2 + j, H);
                const float* row = img + (size_t)yy * W;
                v[j] = __floats2half2_rn(row[gxL], row[gxR]);
            }
            sort5D(v);
            #pragma unroll
            for (int j = 0; j < 5; j++) sc[j][cy][p] = v[j];
        }
    }
    __syncthreads();

    // ---- Phase 1.5: deduplicated pair-merges (each used by two adjacent units) ----
    #pragma unroll
    for (int k = 0; k < 3; k++) {
        const int task = tid + k * NTHREADS;
        if (k < 2 || task < NPTASKS) {     // k<2 always in range (512 < 544)
            const int pk = task % NPAIR;   // pair index 0..16
            const int cy = task / NPAIR;
            __half2 a[5], bb[5];
            #pragma unroll
            for (int j = 0; j < 5; j++) {
                a[j]  = sc[j][cy][2 * pk + 1];
                bb[j] = sc[j][cy][2 * pk + 2];
            }
            __half2 m[10];
            merge55(a, bb, m);
            #pragma unroll
            for (int j = 0; j < 10; j += 2) {
                float2 w;
                w.x = *reinterpret_cast<const float*>(&m[j]);
                w.y = *reinterpret_cast<const float*>(&m[j + 1]);
                *reinterpret_cast<float2*>(&pm[cy][pk][j]) = w;
            }
        }
    }
    __syncthreads();

    // ---- Phase 2: two independent units per thread (rows ty and ty+16) ----
    float* orowA = out + ((size_t)b * H + (y0 + ty)) * W + x0;
    float* orowB = out + ((size_t)b * H + (y0 + ty + TYB)) * W + x0;
    phase2_unit(sc, pm, ty,       tx, orowA);
    phase2_unit(sc, pm, ty + TYB, tx, orowB);
}

} // namespace

extern "C" void kernel_launch(void* const* d_in, const int* in_sizes, int n_in,
                              void* d_out, int out_size) {
    const float* inp = (const float*)d_in[0];
    float* out = (float*)d_out;
    dim3 grid(W / TILE_W, H / TILE_H, B);   // 8 x 16 x 16 = 2048
    dim3 block(TPX, TYB);                   // 16 x 16
    ordfilter_kernel<<<grid, block>>>(inp, out);
}